// round 16
// baseline (speedup 1.0000x reference)
#include <cuda_runtime.h>
#include <cuda_bf16.h>
#include <mma.h>
#include <cstdint>

using namespace nvcuda;

// Problem constants (from reference setup_inputs)
#define MAXN 50000
#define MAXE 800000
#define IN_DIM 768
#define HID 256
#define OUT_DIM 128
#define BATCH 1024
#define NBLK 64            // >= ceil(MAXN/1024)

// ---------------- device scratch (no runtime allocation allowed) -------------
__device__ __align__(16) float g_bufA[MAXN * HID];   // h1, later hs2
__device__ __align__(16) float g_bufB[MAXN * HID];   // hs1
__device__ __align__(16) float g_bufC[MAXN * HID];   // out1
__device__ float g_dinv[MAXN];
__device__ int   g_deg[MAXN];
__device__ int   g_rowptr[MAXN + 1];
__device__ int   g_cursor[MAXN];
__device__ int   g_csrsrc[MAXE];
__device__ int   g_mask[MAXN];
__device__ int   g_blksum[NBLK];
__device__ int   g_blkoff[NBLK];
__device__ int   g_total;
__device__ __align__(16) float g_out2[BATCH * HID];
__device__ int   g_is64;
__device__ int   g_rows[MAXN];
__device__ int   g_nrows;
// pre-transposed + bf16-split weights: [N][K] K-major
__device__ __align__(16) __nv_bfloat16 g_w1t_hi[HID * IN_DIM];
__device__ __align__(16) __nv_bfloat16 g_w1t_lo[HID * IN_DIM];
__device__ __align__(16) __nv_bfloat16 g_wg1t_hi[HID * HID];
__device__ __align__(16) __nv_bfloat16 g_wg1t_lo[HID * HID];
__device__ __align__(16) __nv_bfloat16 g_wg2t_hi[HID * HID];
__device__ __align__(16) __nv_bfloat16 g_wg2t_lo[HID * HID];

// ---------------- cp.async helpers (sm_80+, family-safe) ----------------------
__device__ __forceinline__ void cp16(void* dst, const void* src) {
    uint32_t d = (uint32_t)__cvta_generic_to_shared(dst);
    asm volatile("cp.async.cg.shared.global [%0], [%1], 16;" :: "r"(d), "l"(src));
}
#define CP_COMMIT() asm volatile("cp.async.commit_group;" ::: "memory")
#define CP_WAIT0()  asm volatile("cp.async.wait_group 0;" ::: "memory")

// ---------------- edge dtype probe -------------------------------------------
__global__ void detect_dtype(const unsigned* __restrict__ buf) {
    __shared__ int cnt;
    if (threadIdx.x == 0) cnt = 0;
    __syncthreads();
    int z = 0;
    for (int i = threadIdx.x; i < 1024; i += blockDim.x)
        if (buf[2 * i + 1] == 0u) z++;
    atomicAdd(&cnt, z);
    __syncthreads();
    if (threadIdx.x == 0) g_is64 = (cnt > 512) ? 1 : 0;
}

__device__ __forceinline__ int edge_src(const void* e, int i) {
    return g_is64 ? (int)((const long long*)e)[i] : ((const int*)e)[i];
}
__device__ __forceinline__ int edge_dst(const void* e, int i, int E) {
    return g_is64 ? (int)((const long long*)e)[(size_t)E + i]
                  : ((const int*)e)[(size_t)E + i];
}

// ---------------- graph preprocessing ----------------------------------------
__global__ void zero_int2(int n) {
    int i = blockIdx.x * blockDim.x + threadIdx.x;
    if (i < n) { g_deg[i] = 0; g_mask[i] = 0; }
    if (i == 0) g_nrows = 0;
}

// merged: in-degree histogram + layer-1 liveness mask
__global__ void edge_pass(const void* __restrict__ eidx, int E, int Nn) {
    int e = blockIdx.x * blockDim.x + threadIdx.x;
    if (e < E) {
        int d = edge_dst(eidx, e, E);
        if ((unsigned)d < (unsigned)Nn) {
            atomicAdd(&g_deg[d], 1);
            if (d < BATCH) {
                int s = edge_src(eidx, e);
                if ((unsigned)s < (unsigned)Nn) g_mask[s] = 1;
            }
        }
    }
    if (e < BATCH) g_mask[e] = 1;
}

// hierarchical scan, phase 1: per-block shuffle scan (also computes dinv)
__global__ void scan_local(int n) {
    __shared__ int warpsum[32];
    int b = blockIdx.x, t = threadIdx.x;
    int idx = b * 1024 + t;
    int v = (idx < n) ? g_deg[idx] : 0;
    if (idx < n) g_dinv[idx] = rsqrtf((float)(v + 1));   // +1 self loop
    int lane = t & 31, w = t >> 5;
    int inc = v;
    #pragma unroll
    for (int o = 1; o < 32; o <<= 1) {
        int x = __shfl_up_sync(0xffffffffu, inc, o);
        if (lane >= o) inc += x;
    }
    if (lane == 31) warpsum[w] = inc;
    __syncthreads();
    if (w == 0) {
        int s = warpsum[lane];
        #pragma unroll
        for (int o = 1; o < 32; o <<= 1) {
            int x = __shfl_up_sync(0xffffffffu, s, o);
            if (lane >= o) s += x;
        }
        warpsum[lane] = s;
    }
    __syncthreads();
    int woff = (w == 0) ? 0 : warpsum[w - 1];
    if (idx < n) g_rowptr[idx] = woff + inc - v;
    if (t == 1023) g_blksum[b] = woff + inc;
}

// phase 2: tiny serial scan of block sums
__global__ void scan_blk(int nb) {
    __shared__ int s[NBLK];
    int t = threadIdx.x;
    if (t < NBLK) s[t] = (t < nb) ? g_blksum[t] : 0;
    __syncthreads();
    if (t == 0) {
        int run = 0;
        for (int i = 0; i < nb; i++) { int v = s[i]; g_blkoff[i] = run; run += v; }
        g_total = run;
    }
}

// phase 3: add block offsets, produce rowptr + cursor; also compact masked rows
__global__ void scan_add(int n) {
    int idx = blockIdx.x * blockDim.x + threadIdx.x;
    if (idx < n) {
        int v = g_rowptr[idx] + g_blkoff[idx >> 10];
        g_rowptr[idx] = v;
        g_cursor[idx] = v;
        if (g_mask[idx]) {
            int p = atomicAdd(&g_nrows, 1);
            g_rows[p] = idx;
        }
    }
    if (idx == 0) g_rowptr[n] = g_total;
}

__global__ void fill_csr(const void* __restrict__ eidx, int E, int Nn) {
    int e = blockIdx.x * blockDim.x + threadIdx.x;
    if (e < E) {
        int d = edge_dst(eidx, e, E);
        int s = edge_src(eidx, e);
        if ((unsigned)d < (unsigned)Nn && (unsigned)s < (unsigned)Nn) {
            int p = atomicAdd(&g_cursor[d], 1);
            if ((unsigned)p < (unsigned)MAXE) g_csrsrc[p] = s;
        }
    }
}

// ---------------- weight transpose + bf16 hi/lo split (tiled, coalesced) ------
__global__ void w_split_t(const float* __restrict__ W, int K, int N,
                          __nv_bfloat16* __restrict__ hi, __nv_bfloat16* __restrict__ lo) {
    __shared__ float tile[32][33];
    int n0 = blockIdx.x * 32, k0 = blockIdx.y * 32;
    int tx = threadIdx.x, ty = threadIdx.y;
    #pragma unroll
    for (int i = ty; i < 32; i += 8)
        tile[i][tx] = W[(size_t)(k0 + i) * N + n0 + tx];
    __syncthreads();
    #pragma unroll
    for (int i = ty; i < 32; i += 8) {
        float v = tile[tx][i];                 // = W[k0+tx][n0+i]
        __nv_bfloat16 h = __float2bfloat16(v);
        size_t o = (size_t)(n0 + i) * K + k0 + tx;   // coalesced in tx
        hi[o] = h;
        lo[o] = __float2bfloat16(v - __bfloat162float(h));
    }
}

// ---------------- WMMA bf16 split GEMM (4 warps, 64x64 warp tile) -------------
// C[m0+.., 256] = A @ Wt^T  (Wt stored [256, K] K-major, bf16 hi/lo split)
// 3-term split: Ahi*Bhi + Alo*Bhi + Ahi*Blo with fp32 accumulation.
// epi==0: C = relu(acc + P[n]) ;  epi==1: C = acc * P[row]
// m0: M-tile offset (rows m0 + blockIdx.y*128) for chunked stream pipelining.
#define WG_PAD 40
#define WG_ROWB (WG_PAD * 2)            // 80 bytes per row
#define WG_BUF  (128 * WG_ROWB)         // 10240 bytes per matrix buffer
#define WG_AHI 0
#define WG_ALO (WG_BUF)
#define WG_BHI (2 * WG_BUF)
#define WG_BLO (3 * WG_BUF)
#define WG_STAGE (4 * WG_BUF)           // 40960
#define WG_CPAD 132
#define WG_SMEM_TOTAL (2 * WG_STAGE)    // 81920 (> 128*132*4 = 67584 C tile)

__global__ void __launch_bounds__(128, 2)
gemm_wmma(const float* __restrict__ A,
          const __nv_bfloat16* __restrict__ Bhi, const __nv_bfloat16* __restrict__ Blo,
          const float* __restrict__ P, float* __restrict__ C,
          int M, int K, int epi, int m0,
          const int* __restrict__ rows, const int* __restrict__ nrp)
{
    extern __shared__ char smem[];
    const int tid = threadIdx.x;
    const int wid = tid >> 5;
    const int bn  = blockIdx.x * 128;          // 0 or 128
    const int bm  = m0 + blockIdx.y * 128;
    const int limit = nrp ? *nrp : M;
    if (bm >= limit) return;

    const int wr = wid & 1;      // warp row: 2 x 64 M
    const int wc = wid >> 1;     // warp col: 2 x 64 N

    wmma::fragment<wmma::accumulator, 16, 16, 16, float> acc[4][4];
    #pragma unroll
    for (int mt = 0; mt < 4; mt++)
        #pragma unroll
        for (int nt = 0; nt < 4; nt++)
            wmma::fill_fragment(acc[mt][nt], 0.0f);

    // ---- stage fill: A 128x32 fp32 -> bf16 hi/lo; B 128x32 via cp.async
    auto fillA = [&](int stage, int kc) {
        char* sp = smem + stage * WG_STAGE;
        __nv_bfloat16* sAhi = (__nv_bfloat16*)(sp + WG_AHI);
        __nv_bfloat16* sAlo = (__nv_bfloat16*)(sp + WG_ALO);
        #pragma unroll
        for (int it = 0; it < 8; ++it) {
            int idx = it * 128 + tid;           // 0..1023
            int r = idx >> 3, g = (idx & 7) * 4;
            float4 v = make_float4(0.f, 0.f, 0.f, 0.f);
            int rt = bm + r;
            if (rt < limit) {
                int gr = rows ? rows[rt] : rt;
                v = *(const float4*)(A + (size_t)gr * K + kc + g);
            }
            float f[4] = {v.x, v.y, v.z, v.w};
            __nv_bfloat16 hb[4], lb[4];
            #pragma unroll
            for (int j = 0; j < 4; ++j) {
                hb[j] = __float2bfloat16(f[j]);
                lb[j] = __float2bfloat16(f[j] - __bfloat162float(hb[j]));
            }
            *(uint2*)(sAhi + r * WG_PAD + g) = *(uint2*)hb;
            *(uint2*)(sAlo + r * WG_PAD + g) = *(uint2*)lb;
        }
    };
    auto fillB = [&](int stage, int kc) {
        char* sp = smem + stage * WG_STAGE;
        __nv_bfloat16* sBhi = (__nv_bfloat16*)(sp + WG_BHI);
        __nv_bfloat16* sBlo = (__nv_bfloat16*)(sp + WG_BLO);
        #pragma unroll
        for (int it = 0; it < 4; ++it) {
            int idx = it * 128 + tid;           // 0..511
            int r = idx >> 2, g = (idx & 3) * 8;   // 4 x 16B per row of 32 bf16
            cp16(sBhi + r * WG_PAD + g, Bhi + (size_t)(bn + r) * K + kc + g);
            cp16(sBlo + r * WG_PAD + g, Blo + (size_t)(bn + r) * K + kc + g);
        }
    };

    fillA(0, 0); fillB(0, 0); CP_COMMIT();
    CP_WAIT0();
    __syncthreads();

    int cur = 0;
    for (int kc = 0; kc < K; kc += 32) {
        const bool has_next = (kc + 32 < K);
        if (has_next) { fillA(cur ^ 1, kc + 32); fillB(cur ^ 1, kc + 32); CP_COMMIT(); }

        char* sp = smem + cur * WG_STAGE;
        const __nv_bfloat16* sAhi = (const __nv_bfloat16*)(sp + WG_AHI);
        const __nv_bfloat16* sAlo = (const __nv_bfloat16*)(sp + WG_ALO);
        const __nv_bfloat16* sBhi = (const __nv_bfloat16*)(sp + WG_BHI);
        const __nv_bfloat16* sBlo = (const __nv_bfloat16*)(sp + WG_BLO);

        #pragma unroll
        for (int k0 = 0; k0 < 32; k0 += 16) {
            wmma::fragment<wmma::matrix_b, 16, 16, 16, __nv_bfloat16, wmma::col_major> bhi[4], blo[4];
            #pragma unroll
            for (int nt = 0; nt < 4; nt++) {
                wmma::load_matrix_sync(bhi[nt], sBhi + (wc * 64 + nt * 16) * WG_PAD + k0, WG_PAD);
                wmma::load_matrix_sync(blo[nt], sBlo + (wc * 64 + nt * 16) * WG_PAD + k0, WG_PAD);
            }
            #pragma unroll
            for (int mt = 0; mt < 4; mt++) {
                wmma::fragment<wmma::matrix_a, 16, 16, 16, __nv_bfloat16, wmma::row_major> ahi, alo;
                int ar = wr * 64 + mt * 16;
                wmma::load_matrix_sync(ahi, sAhi + ar * WG_PAD + k0, WG_PAD);
                wmma::load_matrix_sync(alo, sAlo + ar * WG_PAD + k0, WG_PAD);
                #pragma unroll
                for (int nt = 0; nt < 4; nt++)
                    wmma::mma_sync(acc[mt][nt], ahi, bhi[nt], acc[mt][nt]);
                #pragma unroll
                for (int nt = 0; nt < 4; nt++)
                    wmma::mma_sync(acc[mt][nt], alo, bhi[nt], acc[mt][nt]);
                #pragma unroll
                for (int nt = 0; nt < 4; nt++)
                    wmma::mma_sync(acc[mt][nt], ahi, blo[nt], acc[mt][nt]);
            }
        }
        if (has_next) CP_WAIT0();
        __syncthreads();
        cur ^= 1;
    }

    // ---- epilogue through smem C tile (reuse operand smem: 128x132 f32)
    float* Cs = (float*)smem;
    #pragma unroll
    for (int mt = 0; mt < 4; mt++)
        #pragma unroll
        for (int nt = 0; nt < 4; nt++)
            wmma::store_matrix_sync(Cs + (wr * 64 + mt * 16) * WG_CPAD + wc * 64 + nt * 16,
                                    acc[mt][nt], WG_CPAD, wmma::mem_row_major);
    __syncthreads();

    // 128 threads: each handles one full row of 128 floats
    {
        int r = tid;
        int rt = bm + r;
        if (rt < limit) {
            int gr = rows ? rows[rt] : rt;
            float* cp = C + (size_t)gr * 256 + bn;
            const float* cs = Cs + r * WG_CPAD;
            if (epi == 0) {
                #pragma unroll 8
                for (int j = 0; j < 128; j += 4) {
                    float4 o;
                    o.x = fmaxf(cs[j + 0] + P[bn + j + 0], 0.f);
                    o.y = fmaxf(cs[j + 1] + P[bn + j + 1], 0.f);
                    o.z = fmaxf(cs[j + 2] + P[bn + j + 2], 0.f);
                    o.w = fmaxf(cs[j + 3] + P[bn + j + 3], 0.f);
                    *(float4*)(cp + j) = o;
                }
            } else {
                float dv = P[gr];
                #pragma unroll 8
                for (int j = 0; j < 128; j += 4) {
                    float4 o;
                    o.x = cs[j + 0] * dv;
                    o.y = cs[j + 1] * dv;
                    o.z = cs[j + 2] * dv;
                    o.w = cs[j + 3] * dv;
                    *(float4*)(cp + j) = o;
                }
            }
        }
    }
}

// ---------------- GCN aggregation (warp per node, 256 features) ---------------
__global__ void aggregate(const float* __restrict__ hs,
                          const float* __restrict__ bias,
                          int use_mask,
                          float* __restrict__ out, int n_nodes)
{
    int warp = (blockIdx.x * blockDim.x + threadIdx.x) >> 5;
    int lane = threadIdx.x & 31;
    if (warp >= n_nodes) return;
    if (use_mask && !g_mask[warp]) return;
    const int i = warp;
    const int f = lane * 8;

    float4 acc0 = *(const float4*)(hs + (size_t)i * HID + f);
    float4 acc1 = *(const float4*)(hs + (size_t)i * HID + f + 4);

    int beg = g_rowptr[i], end = g_rowptr[i + 1];
    for (int e = beg; e < end; ++e) {
        int s = g_csrsrc[e];
        float4 v0 = *(const float4*)(hs + (size_t)s * HID + f);
        float4 v1 = *(const float4*)(hs + (size_t)s * HID + f + 4);
        acc0.x += v0.x; acc0.y += v0.y; acc0.z += v0.z; acc0.w += v0.w;
        acc1.x += v1.x; acc1.y += v1.y; acc1.z += v1.z; acc1.w += v1.w;
    }
    float dv = g_dinv[i];
    float4 o0, o1;
    o0.x = acc0.x * dv + bias[f + 0];
    o0.y = acc0.y * dv + bias[f + 1];
    o0.z = acc0.z * dv + bias[f + 2];
    o0.w = acc0.w * dv + bias[f + 3];
    o1.x = acc1.x * dv + bias[f + 4];
    o1.y = acc1.y * dv + bias[f + 5];
    o1.z = acc1.z * dv + bias[f + 6];
    o1.w = acc1.w * dv + bias[f + 7];
    *(float4*)(out + (size_t)i * HID + f)     = o0;
    *(float4*)(out + (size_t)i * HID + f + 4) = o1;
}

// ---------------- fused head: h3 = relu(out2@W2+b2); logits = h3@Wc+bc --------
__global__ void __launch_bounds__(128)
fused_head(const float* __restrict__ out2, const float* __restrict__ W2,
           const float* __restrict__ b2, const float* __restrict__ Wc,
           const float* __restrict__ bc, float* __restrict__ out)
{
    __shared__ float srow[HID];
    __shared__ float sh3[OUT_DIM];
    int row = blockIdx.x, t = threadIdx.x;
    srow[t]       = out2[(size_t)row * HID + t];
    srow[t + 128] = out2[(size_t)row * HID + t + 128];
    __syncthreads();
    float acc = b2[t];
    #pragma unroll 8
    for (int k = 0; k < HID; k++)
        acc = fmaf(srow[k], W2[k * OUT_DIM + t], acc);
    sh3[t] = fmaxf(acc, 0.f);
    __syncthreads();
    int w = t >> 5, lane = t & 31;
    if (w < 2) {
        float a = 0.f;
        #pragma unroll
        for (int k = lane; k < OUT_DIM; k += 32)
            a = fmaf(sh3[k], Wc[k * 2 + w], a);
        #pragma unroll
        for (int o = 16; o; o >>= 1) a += __shfl_down_sync(0xffffffffu, a, o);
        if (lane == 0) out[row * 2 + w] = a + bc[w];
    }
}

// ---------------- launch -------------------------------------------------------
extern "C" void kernel_launch(void* const* d_in, const int* in_sizes, int n_in,
                              void* d_out, int out_size) {
    const float* x    = (const float*)d_in[0];
    const void*  eidx = d_in[1];
    const float* W1   = (const float*)d_in[2];
    const float* b1   = (const float*)d_in[3];
    const float* Wg1  = (const float*)d_in[4];
    const float* bg1  = (const float*)d_in[5];
    const float* Wg2  = (const float*)d_in[6];
    const float* bg2  = (const float*)d_in[7];
    const float* W2   = (const float*)d_in[8];
    const float* b2   = (const float*)d_in[9];
    const float* Wc   = (const float*)d_in[10];
    const float* bc   = (const float*)d_in[11];

    const int N = in_sizes[0] / IN_DIM;   // 50000
    const int E = in_sizes[1] / 2;        // 800000

    float *bufA, *bufB, *bufC, *out2, *dinvp;
    int *rowsp, *nrowsp;
    __nv_bfloat16 *w1h, *w1l, *wg1h, *wg1l, *wg2h, *wg2l;
    cudaGetSymbolAddress((void**)&bufA,   g_bufA);
    cudaGetSymbolAddress((void**)&bufB,   g_bufB);
    cudaGetSymbolAddress((void**)&bufC,   g_bufC);
    cudaGetSymbolAddress((void**)&out2,   g_out2);
    cudaGetSymbolAddress((void**)&dinvp,  g_dinv);
    cudaGetSymbolAddress((void**)&rowsp,  g_rows);
    cudaGetSymbolAddress((void**)&nrowsp, g_nrows);
    cudaGetSymbolAddress((void**)&w1h,    g_w1t_hi);
    cudaGetSymbolAddress((void**)&w1l,    g_w1t_lo);
    cudaGetSymbolAddress((void**)&wg1h,   g_wg1t_hi);
    cudaGetSymbolAddress((void**)&wg1l,   g_wg1t_lo);
    cudaGetSymbolAddress((void**)&wg2h,   g_wg2t_hi);
    cudaGetSymbolAddress((void**)&wg2l,   g_wg2t_lo);

    cudaFuncSetAttribute(gemm_wmma, cudaFuncAttributeMaxDynamicSharedMemorySize,
                         WG_SMEM_TOTAL);

    const int TB = 256;
    const int gE = (E + TB - 1) / TB;
    const int gN = (N + TB - 1) / TB;
    const int nSB = (N + 1023) / 1024;    // scan blocks (49)
    const int nMT = (N + 127) / 128;      // 391 M-tiles
    const int halfMT = (nMT + 1) / 2;     // 196
    const int restMT = nMT - halfMT;      // 195
    const int m0b = halfMT * 128;         // 25088

    cudaStream_t sB;
    cudaStreamCreate(&sB);
    cudaEvent_t evFork, ev1a, ev1b, evJoin;
    cudaEventCreateWithFlags(&evFork, cudaEventDisableTiming);
    cudaEventCreateWithFlags(&ev1a,   cudaEventDisableTiming);
    cudaEventCreateWithFlags(&ev1b,   cudaEventDisableTiming);
    cudaEventCreateWithFlags(&evJoin, cudaEventDisableTiming);

    // ---- fork
    cudaEventRecord(evFork, 0);
    cudaStreamWaitEvent(sB, evFork, 0);

    // ---- branch B (side stream): edge preprocessing + Wg splits
    detect_dtype<<<1, 256, 0, sB>>>((const unsigned*)eidx);
    zero_int2<<<gN, TB, 0, sB>>>(N);
    edge_pass<<<gE, TB, 0, sB>>>(eidx, E, N);
    scan_local<<<nSB, 1024, 0, sB>>>(N);
    scan_blk<<<1, NBLK, 0, sB>>>(nSB);
    scan_add<<<nSB, 1024, 0, sB>>>(N);
    fill_csr<<<gE, TB, 0, sB>>>(eidx, E, N);
    {
        dim3 blk(32, 8);
        dim3 grd(HID / 32, HID / 32);
        w_split_t<<<grd, blk, 0, sB>>>(Wg1, HID, HID, wg1h, wg1l);
        w_split_t<<<grd, blk, 0, sB>>>(Wg2, HID, HID, wg2h, wg2l);
    }

    // ---- branch A (main stream): W1 split + GEMM1 in two M-chunks
    {
        dim3 blk(32, 8);
        dim3 grd(HID / 32, IN_DIM / 32);
        w_split_t<<<grd, blk>>>(W1, IN_DIM, HID, w1h, w1l);
    }
    {
        dim3 grid(2, halfMT);
        gemm_wmma<<<grid, 128, WG_SMEM_TOTAL>>>(x, w1h, w1l, b1, bufA,
                                                N, IN_DIM, 0, 0, nullptr, nullptr);
    }
    cudaEventRecord(ev1a, 0);
    {
        dim3 grid(2, restMT);
        gemm_wmma<<<grid, 128, WG_SMEM_TOTAL>>>(x, w1h, w1l, b1, bufA,
                                                N, IN_DIM, 0, m0b, nullptr, nullptr);
    }
    cudaEventRecord(ev1b, 0);

    // ---- GEMM2 chunks in side stream, pipelined against GEMM1's 2nd chunk
    cudaStreamWaitEvent(sB, ev1a, 0);
    {
        dim3 grid(2, halfMT);
        gemm_wmma<<<grid, 128, WG_SMEM_TOTAL, sB>>>(bufA, wg1h, wg1l, dinvp, bufB,
                                                    N, HID, 1, 0, nullptr, nullptr);
    }
    cudaStreamWaitEvent(sB, ev1b, 0);
    {
        dim3 grid(2, restMT);
        gemm_wmma<<<grid, 128, WG_SMEM_TOTAL, sB>>>(bufA, wg1h, wg1l, dinvp, bufB,
                                                    N, HID, 1, m0b, nullptr, nullptr);
    }
    cudaEventRecord(evJoin, sB);

    // ---- join: aggregation onward needs all of hs1 + CSR
    cudaStreamWaitEvent(0, evJoin, 0);

    // out1 = aggregate (masked nodes only)
    aggregate<<<(N * 32 + TB - 1) / TB, TB>>>(bufB, bg1, 1, bufC, N);

    // hs2 = dinv ⊙ (out1 @ Wg2) on compacted masked rows
    {
        dim3 grid(2, nMT);
        gemm_wmma<<<grid, 128, WG_SMEM_TOTAL>>>(bufC, wg2h, wg2l, dinvp, bufA,
                                                N, HID, 1, 0, rowsp, nrowsp);
    }
    // out2 = aggregate first BATCH nodes
    aggregate<<<(BATCH * 32 + TB - 1) / TB, TB>>>(bufA, bg2, 0, out2, BATCH);

    // logits = relu(out2@W2+b2) @ Wc + bc          [1024, 2]
    fused_head<<<BATCH, 128>>>(out2, W2, b2, Wc, bc, (float*)d_out);
}

// round 17
// speedup vs baseline: 1.0933x; 1.0933x over previous
#include <cuda_runtime.h>
#include <cuda_bf16.h>
#include <mma.h>
#include <cstdint>

using namespace nvcuda;

// Problem constants (from reference setup_inputs)
#define MAXN 50000
#define MAXE 800000
#define IN_DIM 768
#define HID 256
#define OUT_DIM 128
#define BATCH 1024
#define NBLK 64            // >= ceil(MAXN/1024)

// ---------------- device scratch (no runtime allocation allowed) -------------
__device__ __align__(16) float g_bufA[MAXN * HID];   // h1, later hs2
__device__ __align__(16) float g_bufB[MAXN * HID];   // hs1
__device__ __align__(16) float g_bufC[MAXN * HID];   // out1
__device__ float g_dinv[MAXN];
__device__ int   g_deg[MAXN];
__device__ int   g_rowptr[MAXN + 1];
__device__ int   g_cursor[MAXN];
__device__ int   g_csrsrc[MAXE];
__device__ int   g_mask[MAXN];
__device__ int   g_blksum[NBLK];
__device__ int   g_blkoff[NBLK];
__device__ int   g_total;
__device__ __align__(16) float g_out2[BATCH * HID];
__device__ int   g_is64;
__device__ int   g_rows[MAXN];
__device__ int   g_nrows;
// pre-transposed + bf16-split weights: [N][K] K-major
__device__ __align__(16) __nv_bfloat16 g_w1t_hi[HID * IN_DIM];
__device__ __align__(16) __nv_bfloat16 g_w1t_lo[HID * IN_DIM];
__device__ __align__(16) __nv_bfloat16 g_wg1t_hi[HID * HID];
__device__ __align__(16) __nv_bfloat16 g_wg1t_lo[HID * HID];
__device__ __align__(16) __nv_bfloat16 g_wg2t_hi[HID * HID];
__device__ __align__(16) __nv_bfloat16 g_wg2t_lo[HID * HID];

// ---------------- cp.async helpers (sm_80+, family-safe) ----------------------
__device__ __forceinline__ void cp16(void* dst, const void* src) {
    uint32_t d = (uint32_t)__cvta_generic_to_shared(dst);
    asm volatile("cp.async.cg.shared.global [%0], [%1], 16;" :: "r"(d), "l"(src));
}
#define CP_COMMIT() asm volatile("cp.async.commit_group;" ::: "memory")
#define CP_WAIT0()  asm volatile("cp.async.wait_group 0;" ::: "memory")

// ---------------- edge dtype probe -------------------------------------------
__global__ void detect_dtype(const unsigned* __restrict__ buf) {
    __shared__ int cnt;
    if (threadIdx.x == 0) cnt = 0;
    __syncthreads();
    int z = 0;
    for (int i = threadIdx.x; i < 1024; i += blockDim.x)
        if (buf[2 * i + 1] == 0u) z++;
    atomicAdd(&cnt, z);
    __syncthreads();
    if (threadIdx.x == 0) g_is64 = (cnt > 512) ? 1 : 0;
}

__device__ __forceinline__ int edge_src(const void* e, int i) {
    return g_is64 ? (int)((const long long*)e)[i] : ((const int*)e)[i];
}
__device__ __forceinline__ int edge_dst(const void* e, int i, int E) {
    return g_is64 ? (int)((const long long*)e)[(size_t)E + i]
                  : ((const int*)e)[(size_t)E + i];
}

// ---------------- graph preprocessing ----------------------------------------
__global__ void zero_int2(int n) {
    int i = blockIdx.x * blockDim.x + threadIdx.x;
    if (i < n) { g_deg[i] = 0; g_mask[i] = 0; }
    if (i == 0) g_nrows = 0;
}

// merged: in-degree histogram + layer-1 liveness mask
__global__ void edge_pass(const void* __restrict__ eidx, int E, int Nn) {
    int e = blockIdx.x * blockDim.x + threadIdx.x;
    if (e < E) {
        int d = edge_dst(eidx, e, E);
        if ((unsigned)d < (unsigned)Nn) {
            atomicAdd(&g_deg[d], 1);
            if (d < BATCH) {
                int s = edge_src(eidx, e);
                if ((unsigned)s < (unsigned)Nn) g_mask[s] = 1;
            }
        }
    }
    if (e < BATCH) g_mask[e] = 1;
}

// hierarchical scan, phase 1: per-block shuffle scan (also computes dinv)
__global__ void scan_local(int n) {
    __shared__ int warpsum[32];
    int b = blockIdx.x, t = threadIdx.x;
    int idx = b * 1024 + t;
    int v = (idx < n) ? g_deg[idx] : 0;
    if (idx < n) g_dinv[idx] = rsqrtf((float)(v + 1));   // +1 self loop
    int lane = t & 31, w = t >> 5;
    int inc = v;
    #pragma unroll
    for (int o = 1; o < 32; o <<= 1) {
        int x = __shfl_up_sync(0xffffffffu, inc, o);
        if (lane >= o) inc += x;
    }
    if (lane == 31) warpsum[w] = inc;
    __syncthreads();
    if (w == 0) {
        int s = warpsum[lane];
        #pragma unroll
        for (int o = 1; o < 32; o <<= 1) {
            int x = __shfl_up_sync(0xffffffffu, s, o);
            if (lane >= o) s += x;
        }
        warpsum[lane] = s;
    }
    __syncthreads();
    int woff = (w == 0) ? 0 : warpsum[w - 1];
    if (idx < n) g_rowptr[idx] = woff + inc - v;
    if (t == 1023) g_blksum[b] = woff + inc;
}

// phase 2: tiny serial scan of block sums
__global__ void scan_blk(int nb) {
    __shared__ int s[NBLK];
    int t = threadIdx.x;
    if (t < NBLK) s[t] = (t < nb) ? g_blksum[t] : 0;
    __syncthreads();
    if (t == 0) {
        int run = 0;
        for (int i = 0; i < nb; i++) { int v = s[i]; g_blkoff[i] = run; run += v; }
        g_total = run;
    }
}

// phase 3: add block offsets, produce rowptr + cursor; also compact masked rows
__global__ void scan_add(int n) {
    int idx = blockIdx.x * blockDim.x + threadIdx.x;
    if (idx < n) {
        int v = g_rowptr[idx] + g_blkoff[idx >> 10];
        g_rowptr[idx] = v;
        g_cursor[idx] = v;
        if (g_mask[idx]) {
            int p = atomicAdd(&g_nrows, 1);
            g_rows[p] = idx;
        }
    }
    if (idx == 0) g_rowptr[n] = g_total;
}

__global__ void fill_csr(const void* __restrict__ eidx, int E, int Nn) {
    int e = blockIdx.x * blockDim.x + threadIdx.x;
    if (e < E) {
        int d = edge_dst(eidx, e, E);
        int s = edge_src(eidx, e);
        if ((unsigned)d < (unsigned)Nn && (unsigned)s < (unsigned)Nn) {
            int p = atomicAdd(&g_cursor[d], 1);
            if ((unsigned)p < (unsigned)MAXE) g_csrsrc[p] = s;
        }
    }
}

// ---------------- weight transpose + bf16 hi/lo split (tiled, coalesced) ------
__global__ void w_split_t(const float* __restrict__ W, int K, int N,
                          __nv_bfloat16* __restrict__ hi, __nv_bfloat16* __restrict__ lo) {
    __shared__ float tile[32][33];
    int n0 = blockIdx.x * 32, k0 = blockIdx.y * 32;
    int tx = threadIdx.x, ty = threadIdx.y;
    #pragma unroll
    for (int i = ty; i < 32; i += 8)
        tile[i][tx] = W[(size_t)(k0 + i) * N + n0 + tx];
    __syncthreads();
    #pragma unroll
    for (int i = ty; i < 32; i += 8) {
        float v = tile[tx][i];                 // = W[k0+tx][n0+i]
        __nv_bfloat16 h = __float2bfloat16(v);
        size_t o = (size_t)(n0 + i) * K + k0 + tx;   // coalesced in tx
        hi[o] = h;
        lo[o] = __float2bfloat16(v - __bfloat162float(h));
    }
}

// ---------------- WMMA bf16 split GEMM (4 warps, 64x64 warp tile) -------------
// C[M, 256] = A[M, K] @ Wt^T  (Wt stored [256, K] K-major, bf16 hi/lo split)
// 3-term split: Ahi*Bhi + Alo*Bhi + Ahi*Blo with fp32 accumulation.
// epi==0: C = relu(acc + P[n]) ;  epi==1: C = acc * P[row]
#define WG_PAD 40
#define WG_ROWB (WG_PAD * 2)            // 80 bytes per row
#define WG_BUF  (128 * WG_ROWB)         // 10240 bytes per matrix buffer
#define WG_AHI 0
#define WG_ALO (WG_BUF)
#define WG_BHI (2 * WG_BUF)
#define WG_BLO (3 * WG_BUF)
#define WG_STAGE (4 * WG_BUF)           // 40960
#define WG_CPAD 132
#define WG_SMEM_TOTAL (2 * WG_STAGE)    // 81920 (> 128*132*4 = 67584 C tile)

__global__ void __launch_bounds__(128, 2)
gemm_wmma(const float* __restrict__ A,
          const __nv_bfloat16* __restrict__ Bhi, const __nv_bfloat16* __restrict__ Blo,
          const float* __restrict__ P, float* __restrict__ C,
          int M, int K, int epi,
          const int* __restrict__ rows, const int* __restrict__ nrp)
{
    extern __shared__ char smem[];
    const int tid = threadIdx.x;
    const int wid = tid >> 5;
    const int bn  = blockIdx.x * 128;          // 0 or 128
    const int bm  = blockIdx.y * 128;
    const int limit = nrp ? *nrp : M;
    if (bm >= limit) return;

    const int wr = wid & 1;      // warp row: 2 x 64 M
    const int wc = wid >> 1;     // warp col: 2 x 64 N

    wmma::fragment<wmma::accumulator, 16, 16, 16, float> acc[4][4];
    #pragma unroll
    for (int mt = 0; mt < 4; mt++)
        #pragma unroll
        for (int nt = 0; nt < 4; nt++)
            wmma::fill_fragment(acc[mt][nt], 0.0f);

    // ---- stage fill: A 128x32 fp32 -> bf16 hi/lo; B 128x32 via cp.async
    auto fillA = [&](int stage, int kc) {
        char* sp = smem + stage * WG_STAGE;
        __nv_bfloat16* sAhi = (__nv_bfloat16*)(sp + WG_AHI);
        __nv_bfloat16* sAlo = (__nv_bfloat16*)(sp + WG_ALO);
        #pragma unroll
        for (int it = 0; it < 8; ++it) {
            int idx = it * 128 + tid;           // 0..1023
            int r = idx >> 3, g = (idx & 7) * 4;
            float4 v = make_float4(0.f, 0.f, 0.f, 0.f);
            int rt = bm + r;
            if (rt < limit) {
                int gr = rows ? rows[rt] : rt;
                v = *(const float4*)(A + (size_t)gr * K + kc + g);
            }
            float f[4] = {v.x, v.y, v.z, v.w};
            __nv_bfloat16 hb[4], lb[4];
            #pragma unroll
            for (int j = 0; j < 4; ++j) {
                hb[j] = __float2bfloat16(f[j]);
                lb[j] = __float2bfloat16(f[j] - __bfloat162float(hb[j]));
            }
            *(uint2*)(sAhi + r * WG_PAD + g) = *(uint2*)hb;
            *(uint2*)(sAlo + r * WG_PAD + g) = *(uint2*)lb;
        }
    };
    auto fillB = [&](int stage, int kc) {
        char* sp = smem + stage * WG_STAGE;
        __nv_bfloat16* sBhi = (__nv_bfloat16*)(sp + WG_BHI);
        __nv_bfloat16* sBlo = (__nv_bfloat16*)(sp + WG_BLO);
        #pragma unroll
        for (int it = 0; it < 4; ++it) {
            int idx = it * 128 + tid;           // 0..511
            int r = idx >> 2, g = (idx & 3) * 8;   // 4 x 16B per row of 32 bf16
            cp16(sBhi + r * WG_PAD + g, Bhi + (size_t)(bn + r) * K + kc + g);
            cp16(sBlo + r * WG_PAD + g, Blo + (size_t)(bn + r) * K + kc + g);
        }
    };

    fillA(0, 0); fillB(0, 0); CP_COMMIT();
    CP_WAIT0();
    __syncthreads();

    int cur = 0;
    for (int kc = 0; kc < K; kc += 32) {
        const bool has_next = (kc + 32 < K);
        if (has_next) { fillA(cur ^ 1, kc + 32); fillB(cur ^ 1, kc + 32); CP_COMMIT(); }

        char* sp = smem + cur * WG_STAGE;
        const __nv_bfloat16* sAhi = (const __nv_bfloat16*)(sp + WG_AHI);
        const __nv_bfloat16* sAlo = (const __nv_bfloat16*)(sp + WG_ALO);
        const __nv_bfloat16* sBhi = (const __nv_bfloat16*)(sp + WG_BHI);
        const __nv_bfloat16* sBlo = (const __nv_bfloat16*)(sp + WG_BLO);

        #pragma unroll
        for (int k0 = 0; k0 < 32; k0 += 16) {
            wmma::fragment<wmma::matrix_b, 16, 16, 16, __nv_bfloat16, wmma::col_major> bhi[4], blo[4];
            #pragma unroll
            for (int nt = 0; nt < 4; nt++) {
                wmma::load_matrix_sync(bhi[nt], sBhi + (wc * 64 + nt * 16) * WG_PAD + k0, WG_PAD);
                wmma::load_matrix_sync(blo[nt], sBlo + (wc * 64 + nt * 16) * WG_PAD + k0, WG_PAD);
            }
            #pragma unroll
            for (int mt = 0; mt < 4; mt++) {
                wmma::fragment<wmma::matrix_a, 16, 16, 16, __nv_bfloat16, wmma::row_major> ahi, alo;
                int ar = wr * 64 + mt * 16;
                wmma::load_matrix_sync(ahi, sAhi + ar * WG_PAD + k0, WG_PAD);
                wmma::load_matrix_sync(alo, sAlo + ar * WG_PAD + k0, WG_PAD);
                #pragma unroll
                for (int nt = 0; nt < 4; nt++)
                    wmma::mma_sync(acc[mt][nt], ahi, bhi[nt], acc[mt][nt]);
                #pragma unroll
                for (int nt = 0; nt < 4; nt++)
                    wmma::mma_sync(acc[mt][nt], alo, bhi[nt], acc[mt][nt]);
                #pragma unroll
                for (int nt = 0; nt < 4; nt++)
                    wmma::mma_sync(acc[mt][nt], ahi, blo[nt], acc[mt][nt]);
            }
        }
        if (has_next) CP_WAIT0();
        __syncthreads();
        cur ^= 1;
    }

    // ---- epilogue through smem C tile (reuse operand smem: 128x132 f32)
    float* Cs = (float*)smem;
    #pragma unroll
    for (int mt = 0; mt < 4; mt++)
        #pragma unroll
        for (int nt = 0; nt < 4; nt++)
            wmma::store_matrix_sync(Cs + (wr * 64 + mt * 16) * WG_CPAD + wc * 64 + nt * 16,
                                    acc[mt][nt], WG_CPAD, wmma::mem_row_major);
    __syncthreads();

    // 128 threads: each handles one full row of 128 floats
    {
        int r = tid;
        int rt = bm + r;
        if (rt < limit) {
            int gr = rows ? rows[rt] : rt;
            float* cp = C + (size_t)gr * 256 + bn;
            const float* cs = Cs + r * WG_CPAD;
            if (epi == 0) {
                #pragma unroll 8
                for (int j = 0; j < 128; j += 4) {
                    float4 o;
                    o.x = fmaxf(cs[j + 0] + P[bn + j + 0], 0.f);
                    o.y = fmaxf(cs[j + 1] + P[bn + j + 1], 0.f);
                    o.z = fmaxf(cs[j + 2] + P[bn + j + 2], 0.f);
                    o.w = fmaxf(cs[j + 3] + P[bn + j + 3], 0.f);
                    *(float4*)(cp + j) = o;
                }
            } else {
                float dv = P[gr];
                #pragma unroll 8
                for (int j = 0; j < 128; j += 4) {
                    float4 o;
                    o.x = cs[j + 0] * dv;
                    o.y = cs[j + 1] * dv;
                    o.z = cs[j + 2] * dv;
                    o.w = cs[j + 3] * dv;
                    *(float4*)(cp + j) = o;
                }
            }
        }
    }
}

// ---------------- GCN aggregation (warp per node, 256 features) ---------------
// rows!=nullptr: warp w handles node rows[w], w < *nrp (dense compacted list).
// rows==nullptr: warp w handles node w, w < n_nodes.
__global__ void aggregate(const float* __restrict__ hs,
                          const float* __restrict__ bias,
                          const int* __restrict__ rows, const int* __restrict__ nrp,
                          float* __restrict__ out, int n_nodes)
{
    int warp = (blockIdx.x * blockDim.x + threadIdx.x) >> 5;
    int lane = threadIdx.x & 31;
    int limit = nrp ? *nrp : n_nodes;
    if (warp >= limit) return;
    const int i = rows ? rows[warp] : warp;
    const int f = lane * 8;

    float4 acc0 = *(const float4*)(hs + (size_t)i * HID + f);
    float4 acc1 = *(const float4*)(hs + (size_t)i * HID + f + 4);

    int beg = g_rowptr[i], end = g_rowptr[i + 1];
    for (int e = beg; e < end; ++e) {
        int s = g_csrsrc[e];
        float4 v0 = *(const float4*)(hs + (size_t)s * HID + f);
        float4 v1 = *(const float4*)(hs + (size_t)s * HID + f + 4);
        acc0.x += v0.x; acc0.y += v0.y; acc0.z += v0.z; acc0.w += v0.w;
        acc1.x += v1.x; acc1.y += v1.y; acc1.z += v1.z; acc1.w += v1.w;
    }
    float dv = g_dinv[i];
    float4 o0, o1;
    o0.x = acc0.x * dv + bias[f + 0];
    o0.y = acc0.y * dv + bias[f + 1];
    o0.z = acc0.z * dv + bias[f + 2];
    o0.w = acc0.w * dv + bias[f + 3];
    o1.x = acc1.x * dv + bias[f + 4];
    o1.y = acc1.y * dv + bias[f + 5];
    o1.z = acc1.z * dv + bias[f + 6];
    o1.w = acc1.w * dv + bias[f + 7];
    *(float4*)(out + (size_t)i * HID + f)     = o0;
    *(float4*)(out + (size_t)i * HID + f + 4) = o1;
}

// ---------------- fused head: h3 = relu(out2@W2+b2); logits = h3@Wc+bc --------
__global__ void __launch_bounds__(128)
fused_head(const float* __restrict__ out2, const float* __restrict__ W2,
           const float* __restrict__ b2, const float* __restrict__ Wc,
           const float* __restrict__ bc, float* __restrict__ out)
{
    __shared__ float srow[HID];
    __shared__ float sh3[OUT_DIM];
    int row = blockIdx.x, t = threadIdx.x;
    srow[t]       = out2[(size_t)row * HID + t];
    srow[t + 128] = out2[(size_t)row * HID + t + 128];
    __syncthreads();
    float acc = b2[t];
    #pragma unroll 8
    for (int k = 0; k < HID; k++)
        acc = fmaf(srow[k], W2[k * OUT_DIM + t], acc);
    sh3[t] = fmaxf(acc, 0.f);
    __syncthreads();
    int w = t >> 5, lane = t & 31;
    if (w < 2) {
        float a = 0.f;
        #pragma unroll
        for (int k = lane; k < OUT_DIM; k += 32)
            a = fmaf(sh3[k], Wc[k * 2 + w], a);
        #pragma unroll
        for (int o = 16; o; o >>= 1) a += __shfl_down_sync(0xffffffffu, a, o);
        if (lane == 0) out[row * 2 + w] = a + bc[w];
    }
}

// ---------------- launch -------------------------------------------------------
extern "C" void kernel_launch(void* const* d_in, const int* in_sizes, int n_in,
                              void* d_out, int out_size) {
    const float* x    = (const float*)d_in[0];
    const void*  eidx = d_in[1];
    const float* W1   = (const float*)d_in[2];
    const float* b1   = (const float*)d_in[3];
    const float* Wg1  = (const float*)d_in[4];
    const float* bg1  = (const float*)d_in[5];
    const float* Wg2  = (const float*)d_in[6];
    const float* bg2  = (const float*)d_in[7];
    const float* W2   = (const float*)d_in[8];
    const float* b2   = (const float*)d_in[9];
    const float* Wc   = (const float*)d_in[10];
    const float* bc   = (const float*)d_in[11];

    const int N = in_sizes[0] / IN_DIM;   // 50000
    const int E = in_sizes[1] / 2;        // 800000

    float *bufA, *bufB, *bufC, *out2, *dinvp;
    int *rowsp, *nrowsp;
    __nv_bfloat16 *w1h, *w1l, *wg1h, *wg1l, *wg2h, *wg2l;
    cudaGetSymbolAddress((void**)&bufA,   g_bufA);
    cudaGetSymbolAddress((void**)&bufB,   g_bufB);
    cudaGetSymbolAddress((void**)&bufC,   g_bufC);
    cudaGetSymbolAddress((void**)&out2,   g_out2);
    cudaGetSymbolAddress((void**)&dinvp,  g_dinv);
    cudaGetSymbolAddress((void**)&rowsp,  g_rows);
    cudaGetSymbolAddress((void**)&nrowsp, g_nrows);
    cudaGetSymbolAddress((void**)&w1h,    g_w1t_hi);
    cudaGetSymbolAddress((void**)&w1l,    g_w1t_lo);
    cudaGetSymbolAddress((void**)&wg1h,   g_wg1t_hi);
    cudaGetSymbolAddress((void**)&wg1l,   g_wg1t_lo);
    cudaGetSymbolAddress((void**)&wg2h,   g_wg2t_hi);
    cudaGetSymbolAddress((void**)&wg2l,   g_wg2t_lo);

    cudaFuncSetAttribute(gemm_wmma, cudaFuncAttributeMaxDynamicSharedMemorySize,
                         WG_SMEM_TOTAL);

    const int TB = 256;
    const int gE = (E + TB - 1) / TB;
    const int gN = (N + TB - 1) / TB;
    const int nSB = (N + 1023) / 1024;    // scan blocks (49)
    const int nMT = (N + 127) / 128;      // 391 M-tiles

    // Side stream for the graph-preprocessing branch (independent of GEMM1).
    cudaStream_t sB;
    cudaStreamCreate(&sB);
    cudaEvent_t evFork, evJoin;
    cudaEventCreateWithFlags(&evFork, cudaEventDisableTiming);
    cudaEventCreateWithFlags(&evJoin, cudaEventDisableTiming);

    // ---- fork
    cudaEventRecord(evFork, 0);
    cudaStreamWaitEvent(sB, evFork, 0);

    // ---- branch B (side stream): edge preprocessing + Wg splits
    detect_dtype<<<1, 256, 0, sB>>>((const unsigned*)eidx);
    zero_int2<<<gN, TB, 0, sB>>>(N);
    edge_pass<<<gE, TB, 0, sB>>>(eidx, E, N);
    scan_local<<<nSB, 1024, 0, sB>>>(N);          // also computes dinv
    scan_blk<<<1, NBLK, 0, sB>>>(nSB);
    scan_add<<<nSB, 1024, 0, sB>>>(N);            // + row compaction
    fill_csr<<<gE, TB, 0, sB>>>(eidx, E, N);
    {
        dim3 blk(32, 8);
        dim3 grd(HID / 32, HID / 32);
        w_split_t<<<grd, blk, 0, sB>>>(Wg1, HID, HID, wg1h, wg1l);
        w_split_t<<<grd, blk, 0, sB>>>(Wg2, HID, HID, wg2h, wg2l);
    }
    cudaEventRecord(evJoin, sB);

    // ---- branch A (main stream): W1 split + GEMM1 overlap branch B
    {
        dim3 blk(32, 8);
        dim3 grd(HID / 32, IN_DIM / 32);
        w_split_t<<<grd, blk>>>(W1, IN_DIM, HID, w1h, w1l);
    }
    {
        dim3 grid(2, nMT);
        gemm_wmma<<<grid, 128, WG_SMEM_TOTAL>>>(x, w1h, w1l, b1, bufA,
                                                N, IN_DIM, 0, nullptr, nullptr);
    }

    // ---- join: everything after needs dinv / CSR / Wg splits
    cudaStreamWaitEvent(0, evJoin, 0);

    // hs1 = dinv ⊙ (h1 @ Wg1)                      [N, 256]
    {
        dim3 grid(2, nMT);
        gemm_wmma<<<grid, 128, WG_SMEM_TOTAL>>>(bufA, wg1h, wg1l, dinvp, bufB,
                                                N, HID, 1, nullptr, nullptr);
    }
    // out1 = aggregate over compacted masked-node list (dense warps)
    aggregate<<<(N * 32 + TB - 1) / TB, TB>>>(bufB, bg1, rowsp, nrowsp, bufC, N);

    // hs2 = dinv ⊙ (out1 @ Wg2) on compacted masked rows
    {
        dim3 grid(2, nMT);
        gemm_wmma<<<grid, 128, WG_SMEM_TOTAL>>>(bufC, wg2h, wg2l, dinvp, bufA,
                                                N, HID, 1, rowsp, nrowsp);
    }
    // out2 = aggregate first BATCH nodes
    aggregate<<<(BATCH * 32 + TB - 1) / TB, TB>>>(bufA, bg2, nullptr, nullptr, out2, BATCH);

    // logits = relu(out2@W2+b2) @ Wc + bc          [1024, 2]
    fused_head<<<BATCH, 128>>>(out2, W2, b2, Wc, bc, (float*)d_out);
}